// round 3
// baseline (speedup 1.0000x reference)
#include <cuda_runtime.h>
#include <cstdint>

// PMSN / S4 kernel materialization:
//   out[h,l] = Re[ sum_n Ceff[h,n] * exp(Adt[h,n] * l) ]
//
// Key identity: along an l-stream of fixed stride S, each state's REAL
// contribution y_n[k] = Re(Ceff_n * A_bar_n^(l0 + k*S)) obeys the stable
// order-2 real recurrence
//     y[k] = c1*y[k-1] + c2*y[k-2],  c1 = 2*Re(M), c2 = -|M|^2, M = A_bar^S.
// This replaces the complex-multiply state update (8 fma-lanes/state/elem)
// with 2 fma ops/state/elem.
//
// Layout: one CTA per h (64 threads). Thread tid owns the 4 consecutive
// outputs l = 4*tid + j + 256*k (j=0..3, k=0..15), kept as two packed
// f32x2 streams {j0,j1} and {j2,j3}; one float4 store (STG.128) per step.

#define NSTATE 4
#define BLOCK_T 64
#define STRIDE  256   // 64 threads * 4 elements

typedef unsigned long long u64;

#define PACK2(d, lo, hi)   asm("mov.b64 %0, {%1, %2};" : "=l"(d) : "f"(lo), "f"(hi))
#define UNPACK2(lo, hi, s) asm("mov.b64 {%0, %1}, %2;" : "=f"(lo), "=f"(hi) : "l"(s))
#define MUL2(d, a, b)      asm("mul.rn.f32x2 %0, %1, %2;" : "=l"(d) : "l"(a), "l"(b))
#define ADD2(d, a, b)      asm("add.rn.f32x2 %0, %1, %2;" : "=l"(d) : "l"(a), "l"(b))
#define FMA2(d, a, b, c)   asm("fma.rn.f32x2 %0, %1, %2, %3;" : "=l"(d) : "l"(a), "l"(b), "l"(c))

__global__ __launch_bounds__(BLOCK_T)
void pmsn_kernel(const float* __restrict__ log_dt,
                 const float* __restrict__ log_A_real,
                 const float* __restrict__ A_imag,
                 const float* __restrict__ VinvB_r,
                 const float* __restrict__ VinvB_i,
                 const float* __restrict__ CV_r,
                 const float* __restrict__ CV_i,
                 float* __restrict__ out,
                 int L)
{
    const int h   = blockIdx.x;
    const int tid = threadIdx.x;

    const float dt = __expf(log_dt[h]);

    u64 C1[NSTATE], C2[NSTATE];            // broadcast recurrence coeffs
    u64 s1a[NSTATE], s2a[NSTATE];          // pair {j=0,1}: y[k+1], y[k]
    u64 s1b[NSTATE], s2b[NSTATE];          // pair {j=2,3}

    const float l0f = (float)(4 * tid);

    #pragma unroll
    for (int n = 0; n < NSTATE; n++) {
        const int idx = h * NSTATE + n;
        const float ar = -__expf(log_A_real[idx]);
        const float ai = A_imag[idx];
        const float adr = ar * dt;
        const float adi = ai * dt;

        // A_bar = exp(Adt)
        float sA, cA;
        const float eA = __expf(adr);
        __sincosf(adi, &sA, &cA);
        const float abr = eA * cA;
        const float abi = eA * sA;

        // B_bar = (A_bar - 1) * B / A ;  Ceff = C * B_bar
        const float br = VinvB_r[idx], bi = VinvB_i[idx];
        const float nr = abr - 1.0f, ni = abi;
        const float nb_r = nr * br - ni * bi;
        const float nb_i = nr * bi + ni * br;
        const float inv = 1.0f / (ar * ar + ai * ai);
        const float bb_r = (nb_r * ar + nb_i * ai) * inv;
        const float bb_i = (nb_i * ar - nb_r * ai) * inv;
        const float cr = CV_r[idx], ci = CV_i[idx];
        const float ce_r = cr * bb_r - ci * bb_i;
        const float ce_i = cr * bb_i + ci * bb_r;

        // M = A_bar^STRIDE via 8 complex squarings (no MUFU)
        float mr = abr, mi = abi;
        #pragma unroll
        for (int q = 0; q < 8; q++) {
            const float t_r = mr * mr - mi * mi;
            const float t_i = 2.0f * mr * mi;
            mr = t_r; mi = t_i;
        }
        const float c1 = 2.0f * mr;
        const float c2 = -(mr * mr + mi * mi);
        PACK2(C1[n], c1, c1);
        PACK2(C2[n], c2, c2);

        // z0 = Ceff * A_bar^(4*tid)   (the only per-lane MUFU work)
        float s0, c0;
        const float e0 = __expf(adr * l0f);
        __sincosf(adi * l0f, &s0, &c0);
        const float k0r = e0 * c0, k0i = e0 * s0;
        float z0r = ce_r * k0r - ce_i * k0i;
        float z0i = ce_r * k0i + ce_i * k0r;
        // z1..z3: successive multiplies by A_bar
        const float z1r = z0r * abr - z0i * abi;
        const float z1i = z0r * abi + z0i * abr;
        const float z2r = z1r * abr - z1i * abi;
        const float z2i = z1r * abi + z1i * abr;
        const float z3r = z2r * abr - z2i * abi;
        const float z3i = z2r * abi + z2i * abr;
        // w_j = z_j * M  (value at l0+j+STRIDE)
        const float w0r = z0r * mr - z0i * mi;
        const float w1r = z1r * mr - z1i * mi;
        const float w2r = z2r * mr - z2i * mi;
        const float w3r = z3r * mr - z3i * mi;

        // y[0] = Re(z), y[1] = Re(w)
        PACK2(s2a[n], z0r, z1r);
        PACK2(s2b[n], z2r, z3r);
        PACK2(s1a[n], w0r, w1r);
        PACK2(s1b[n], w2r, w3r);
    }

    float4* o = reinterpret_cast<float4*>(out + (long long)h * L) + tid;
    const int steps = L / STRIDE;   // 16 for L=4096

    #pragma unroll
    for (int k = 0; k < steps; k++) {
        // output = sum_n y_n[k]  (currently in s2)
        u64 ta, tb, ua, ub, va, vb;
        ADD2(ta, s2a[0], s2a[1]);
        ADD2(ua, s2a[2], s2a[3]);
        ADD2(va, ta, ua);
        ADD2(tb, s2b[0], s2b[1]);
        ADD2(ub, s2b[2], s2b[3]);
        ADD2(vb, tb, ub);
        float4 v;
        UNPACK2(v.x, v.y, va);
        UNPACK2(v.z, v.w, vb);
        o[k * (STRIDE / 4)] = v;

        // advance: y[k+2] = c1*y[k+1] + c2*y[k]
        #pragma unroll
        for (int n = 0; n < NSTATE; n++) {
            u64 nxa, nxb;
            MUL2(nxa, C2[n], s2a[n]);
            FMA2(nxa, C1[n], s1a[n], nxa);
            s2a[n] = s1a[n];
            s1a[n] = nxa;
            MUL2(nxb, C2[n], s2b[n]);
            FMA2(nxb, C1[n], s1b[n], nxb);
            s2b[n] = s1b[n];
            s1b[n] = nxb;
        }
    }
}

extern "C" void kernel_launch(void* const* d_in, const int* in_sizes, int n_in,
                              void* d_out, int out_size)
{
    const float* log_dt     = (const float*)d_in[0];
    const float* log_A_real = (const float*)d_in[1];
    const float* A_imag     = (const float*)d_in[2];
    const float* VinvB_r    = (const float*)d_in[3];
    const float* VinvB_i    = (const float*)d_in[4];
    const float* CV_r       = (const float*)d_in[5];
    const float* CV_i       = (const float*)d_in[6];

    const int H = in_sizes[0];            // 2048
    const int L = out_size / H;           // 4096

    pmsn_kernel<<<H, BLOCK_T>>>(log_dt, log_A_real, A_imag,
                                VinvB_r, VinvB_i, CV_r, CV_i,
                                (float*)d_out, L);
}